// round 6
// baseline (speedup 1.0000x reference)
#include <cuda_runtime.h>
#include <cstdint>
#include <math.h>

// Problem constants
constexpr int cB   = 32;
constexpr int cN   = 256;
constexpr int cCIN = 64;
constexpr int cCH  = 128;   // C_H == C_OUT
constexpr int cR   = 5;
constexpr int cJR  = cN * cR;       // 1280
constexpr int cXD  = 1024;
constexpr float cNEG = -9e15f;

constexpr int MASK_WORDS_PER_ROW = cJR / 32;  // 40
constexpr int ATTN_TILE_I = 32;                // i-rows per block
constexpr int N_ITILES = cN / ATTN_TILE_I;     // 8
constexpr int P_STRIDE = 36;                   // padded row stride of transposed s_p (floats)
constexpr int TILE_JR = 16;                    // H rows per smem stage
constexpr int N_STAGES = 3;
constexpr int N_JR_TILES = cJR / TILE_JR;      // 80
// smem floats: s_p 1280*36 + s_dst 1280 + s_src 160 + s_inv 32 + s_mask 1280 + s_h 3*16*128
constexpr int ATTN_SMEM = (cJR * P_STRIDE + cJR + ATTN_TILE_I * cR + ATTN_TILE_I
                           + ATTN_TILE_I * MASK_WORDS_PER_ROW
                           + N_STAGES * TILE_JR * cCH) * 4;   // 219,904 B

// ---------------- device scratch (no cudaMalloc allowed) ----------------
__device__ float    g_h[cB * cN * cR * cCH];            // (b,n,r,c) == row-major (8192, 640)
__device__ float    g_atoms[cB * cN * cCH];             // layer activations (b,n,c)
__device__ float    g_src[cB * cN * cR];
__device__ float    g_dst[cB * cN * cR];
__device__ unsigned g_mask[cB * cN * MASK_WORDS_PER_ROW];
__device__ float    g_pool[cB * 2 * cCH];               // [mean(128) | max(128)] per batch

__device__ __forceinline__ float leaky(float v) { return v >= 0.f ? v : 0.2f * v; }

__device__ __forceinline__ void cp_async16(unsigned int smem_dst, const void* gsrc) {
    asm volatile("cp.async.cg.shared.global [%0], [%1], 16;\n" :: "r"(smem_dst), "l"(gsrc));
}
__device__ __forceinline__ void cp_commit() {
    asm volatile("cp.async.commit_group;\n");
}
template <int N>
__device__ __forceinline__ void cp_wait() {
    asm volatile("cp.async.wait_group %0;\n" :: "n"(N));
}

// packed f32x2 helpers (Blackwell FFMA2 path — PTX only)
__device__ __forceinline__ unsigned long long pack2(float lo, float hi) {
    unsigned long long r;
    asm("mov.b64 %0, {%1, %2};" : "=l"(r) : "f"(lo), "f"(hi));
    return r;
}
__device__ __forceinline__ void fma2(unsigned long long& d, unsigned long long a,
                                     unsigned long long b) {
    asm("fma.rn.f32x2 %0, %1, %2, %0;" : "+l"(d) : "l"(a), "l"(b));
}
__device__ __forceinline__ float2 unpack2(unsigned long long v) {
    float2 r;
    asm("mov.b64 {%0, %1}, %2;" : "=f"(r.x), "=f"(r.y) : "l"(v));
    return r;
}

// ---------------- 1) pack bond mask into bits ----------------
__global__ __launch_bounds__(256) void pack_mask_kernel(const int* __restrict__ bonds) {
    int w = blockIdx.x * blockDim.x + threadIdx.x;     // word index
    if (w >= cB * cN * MASK_WORDS_PER_ROW) return;
    const int4* p = reinterpret_cast<const int4*>(bonds) + w * 8;  // 32 ints
    unsigned m = 0;
#pragma unroll
    for (int q = 0; q < 8; q++) {
        int4 v = p[q];
        m |= (v.x == 1 ? 1u : 0u) << (q * 4 + 0);
        m |= (v.y == 1 ? 1u : 0u) << (q * 4 + 1);
        m |= (v.z == 1 ? 1u : 0u) << (q * 4 + 2);
        m |= (v.w == 1 ? 1u : 0u) << (q * 4 + 3);
    }
    g_mask[w] = m;
}

// ---------------- 2) h = A @ W + bias   (M=8192, N=640, K=64/128) ----------------
template <int K>
__global__ __launch_bounds__(256) void gemm_bias_kernel(const float* __restrict__ A,
                                                        const float* __restrict__ W,
                                                        const float* __restrict__ bias) {
    __shared__ float As[16][64];   // [k][m]
    __shared__ float Bs[16][64];   // [k][n]
    const int t  = threadIdx.x;
    const int tx = t & 15, ty = t >> 4;
    const int bm = blockIdx.y * 64, bn = blockIdx.x * 64;

    unsigned long long accp[4][2];
#pragma unroll
    for (int i = 0; i < 4; i++) { accp[i][0] = 0ull; accp[i][1] = 0ull; }

    const int arow = t >> 2, akq = t & 3;
    const int bkr = t >> 4, bn4 = t & 15;

    for (int bk = 0; bk < K; bk += 16) {
        float4 av = *reinterpret_cast<const float4*>(&A[(bm + arow) * K + bk + akq * 4]);
        As[akq * 4 + 0][arow] = av.x;
        As[akq * 4 + 1][arow] = av.y;
        As[akq * 4 + 2][arow] = av.z;
        As[akq * 4 + 3][arow] = av.w;
        *reinterpret_cast<float4*>(&Bs[bkr][bn4 * 4]) =
            *reinterpret_cast<const float4*>(&W[(bk + bkr) * 640 + bn + bn4 * 4]);
        __syncthreads();
#pragma unroll
        for (int k = 0; k < 16; k++) {
            float4 a  = *reinterpret_cast<float4*>(&As[k][ty * 4]);
            float4 bv = *reinterpret_cast<float4*>(&Bs[k][tx * 4]);
            unsigned long long b01 = pack2(bv.x, bv.y), b23 = pack2(bv.z, bv.w);
            unsigned long long pa;
            pa = pack2(a.x, a.x); fma2(accp[0][0], pa, b01); fma2(accp[0][1], pa, b23);
            pa = pack2(a.y, a.y); fma2(accp[1][0], pa, b01); fma2(accp[1][1], pa, b23);
            pa = pack2(a.z, a.z); fma2(accp[2][0], pa, b01); fma2(accp[2][1], pa, b23);
            pa = pack2(a.w, a.w); fma2(accp[3][0], pa, b01); fma2(accp[3][1], pa, b23);
        }
        __syncthreads();
    }
    float4 bb = *reinterpret_cast<const float4*>(&bias[bn + tx * 4]);
#pragma unroll
    for (int i = 0; i < 4; i++) {
        float2 lo = unpack2(accp[i][0]), hi = unpack2(accp[i][1]);
        float4 o;
        o.x = lo.x + bb.x; o.y = lo.y + bb.y;
        o.z = hi.x + bb.z; o.w = hi.y + bb.w;
        *reinterpret_cast<float4*>(&g_h[(bm + ty * 4 + i) * 640 + bn + tx * 4]) = o;
    }
}

// ---------------- 3) src/dst projections: (b,n,r) dots over c ----------------
__global__ __launch_bounds__(160) void src_dst_kernel(const float* __restrict__ a) {
    const int bn   = blockIdx.x;           // 0..8191
    const int r    = threadIdx.x >> 5;     // warp = relation
    const int lane = threadIdx.x & 31;
    const float* hrow = &g_h[(bn * cR + r) * cCH];
    float4 hv = *reinterpret_cast<const float4*>(&hrow[lane * 4]);
    float4 as = *reinterpret_cast<const float4*>(&a[r * (2 * cCH) + lane * 4]);
    float4 ad = *reinterpret_cast<const float4*>(&a[r * (2 * cCH) + cCH + lane * 4]);
    float s = hv.x * as.x + hv.y * as.y + hv.z * as.z + hv.w * as.w;
    float d = hv.x * ad.x + hv.y * ad.y + hv.z * ad.z + hv.w * ad.w;
#pragma unroll
    for (int o = 16; o; o >>= 1) {
        s += __shfl_xor_sync(0xffffffffu, s, o);
        d += __shfl_xor_sync(0xffffffffu, d, o);
    }
    if (lane == 0) {
        g_src[bn * cR + r] = s;
        g_dst[bn * cR + r] = d;
    }
}

// ---------------- 4) fused masked softmax + aggregation ----------------
// Block: (b, i-tile of 32 rows), 256 threads.
// s_p TRANSPOSED: s_p[jr * P_STRIDE + row]. Phase 2: thread = 1 col x 16 rows;
// p rows arrive as ready f32x2 pairs via broadcast LDS.128; h is one LDS.32 + dup;
// H streamed via 3-stage cp.async ring with ONE barrier per tile.
template <bool LEAKY_OUT>
__global__ __launch_bounds__(256) void attn_kernel() {
    extern __shared__ float sm[];
    float*    s_p    = sm;                               // [1280][36] transposed
    float*    s_dst  = s_p + cJR * P_STRIDE;             // 1280
    float*    s_src  = s_dst + cJR;                      // 32*5
    float*    s_inv  = s_src + ATTN_TILE_I * cR;         // 32
    unsigned* s_mask = reinterpret_cast<unsigned*>(s_inv + ATTN_TILE_I); // 32*40 words
    float*    s_h    = reinterpret_cast<float*>(s_mask + ATTN_TILE_I * MASK_WORDS_PER_ROW);
                                                         // 3 * 16 * 128 (16B aligned)

    const int b  = blockIdx.x >> 3;
    const int i0 = (blockIdx.x & 7) * ATTN_TILE_I;
    const int t  = threadIdx.x;

    const float* hbase = &g_h[(size_t)b * cJR * cCH];
    const unsigned int s_h_addr = (unsigned int)__cvta_generic_to_shared(s_h);

    // issue the first two H tiles immediately (latency hidden under phase 1)
#pragma unroll
    for (int tile = 0; tile < 2; tile++) {
        const float* src = hbase + tile * TILE_JR * cCH;
        unsigned int dst = s_h_addr + tile * (TILE_JR * cCH * 4);
#pragma unroll
        for (int q = 0; q < 2; q++) {
            int idx = t + 256 * q;
            int r = idx >> 5, c4 = idx & 31;
            cp_async16(dst + (r * cCH + c4 * 4) * 4, src + r * cCH + c4 * 4);
        }
        cp_commit();
    }

    for (int idx = t; idx < cJR; idx += 256) s_dst[idx] = g_dst[b * cJR + idx];
    if (t < ATTN_TILE_I * cR) s_src[t] = g_src[(b * cN + i0) * cR + t];
    for (int idx = t; idx < ATTN_TILE_I * MASK_WORDS_PER_ROW; idx += 256)
        s_mask[idx] = g_mask[(b * cN + i0) * MASK_WORDS_PER_ROW + idx];
    __syncthreads();

    // ---- phase 1: masked leaky logits -> max -> exp -> sum (8 threads / row)
    {
        const int row = t >> 3, l8 = t & 7;
        const float* srcr = s_src + row * cR;
        const unsigned* mrow = s_mask + row * MASK_WORDS_PER_ROW;

        float mx = cNEG;
        for (int e = l8; e < cJR; e += 8) {
            int r = e % 5;
            float v = leaky(srcr[r] + s_dst[e]);
            unsigned bit = (mrow[e >> 5] >> (e & 31)) & 1u;
            v = bit ? v : cNEG;
            s_p[e * P_STRIDE + row] = v;
            mx = fmaxf(mx, v);
        }
#pragma unroll
        for (int o = 4; o; o >>= 1) mx = fmaxf(mx, __shfl_xor_sync(0xffffffffu, mx, o));

        float sum = 0.f;
        for (int e = l8; e < cJR; e += 8) {
            float ev = __expf(s_p[e * P_STRIDE + row] - mx);
            s_p[e * P_STRIDE + row] = ev;
            sum += ev;
        }
#pragma unroll
        for (int o = 4; o; o >>= 1) sum += __shfl_xor_sync(0xffffffffu, sum, o);
        if (l8 == 0) s_inv[row] = 1.f / sum;
    }

    // ---- phase 2: out[32][128] = P^T-stored @ H.  Thread: col = t&127, 16 rows.
    {
        const int col  = t & 127;
        const int half = t >> 7;              // rows half*16 .. half*16+15
        unsigned long long acc[8];
#pragma unroll
        for (int k = 0; k < 8; k++) acc[k] = 0ull;

        const float* pbase = s_p + half * 16;

        for (int tile = 0; tile < N_JR_TILES; tile++) {
            cp_wait<1>();
            __syncthreads();                  // tile ready AND compute of tile-1 done everywhere
            if (tile + 2 < N_JR_TILES) {
                // stage (tile+2)%3 == (tile-1)%3: its compute finished before this barrier
                const float* src = hbase + (tile + 2) * TILE_JR * cCH;
                unsigned int dst = s_h_addr + ((tile + 2) % N_STAGES) * (TILE_JR * cCH * 4);
#pragma unroll
                for (int q = 0; q < 2; q++) {
                    int idx = t + 256 * q;
                    int r = idx >> 5, cc = idx & 31;
                    cp_async16(dst + (r * cCH + cc * 4) * 4, src + r * cCH + cc * 4);
                }
            }
            cp_commit();                      // exactly one group per iteration

            const float* hh = s_h + (tile % N_STAGES) * (TILE_JR * cCH) + col;
            const float* pp = pbase + tile * TILE_JR * P_STRIDE;
#pragma unroll
            for (int j = 0; j < TILE_JR; j++) {
                float hval = hh[j * cCH];
                unsigned long long h2 = pack2(hval, hval);
                ulonglong2 qa = *reinterpret_cast<const ulonglong2*>(pp + j * P_STRIDE);      // rows 0-3
                ulonglong2 qb = *reinterpret_cast<const ulonglong2*>(pp + j * P_STRIDE + 4);  // rows 4-7
                ulonglong2 qc = *reinterpret_cast<const ulonglong2*>(pp + j * P_STRIDE + 8);  // rows 8-11
                ulonglong2 qd = *reinterpret_cast<const ulonglong2*>(pp + j * P_STRIDE + 12); // rows 12-15
                fma2(acc[0], qa.x, h2); fma2(acc[1], qa.y, h2);
                fma2(acc[2], qb.x, h2); fma2(acc[3], qb.y, h2);
                fma2(acc[4], qc.x, h2); fma2(acc[5], qc.y, h2);
                fma2(acc[6], qd.x, h2); fma2(acc[7], qd.y, h2);
            }
        }

        float* outb = &g_atoms[(b * cN + i0 + half * 16) * cCH + col];
#pragma unroll
        for (int k = 0; k < 8; k++) {
            float2 v = unpack2(acc[k]);
            const int r0 = half * 16 + 2 * k;
            float o0 = v.x * s_inv[r0];
            float o1 = v.y * s_inv[r0 + 1];
            if (LEAKY_OUT) { o0 = leaky(o0); o1 = leaky(o1); }
            outb[(2 * k) * cCH]     = o0;
            outb[(2 * k + 1) * cCH] = o1;
        }
    }
}

// ---------------- 5) mean/max pooling over nodes ----------------
__global__ __launch_bounds__(512) void pool_kernel() {
    __shared__ float s_sum[4][cCH];
    __shared__ float s_max[4][cCH];
    const int b  = blockIdx.x;
    const int c  = threadIdx.x & 127;
    const int ch = threadIdx.x >> 7;   // 0..3, 64 nodes each
    float sum = 0.f, mx = -3.4e38f;
    for (int n = ch * 64; n < ch * 64 + 64; n++) {
        float v = g_atoms[(b * cN + n) * cCH + c];
        sum += v;
        mx = fmaxf(mx, v);
    }
    s_sum[ch][c] = sum;
    s_max[ch][c] = mx;
    __syncthreads();
    if (ch == 0) {
        sum = (s_sum[0][c] + s_sum[1][c]) + (s_sum[2][c] + s_sum[3][c]);
        mx = fmaxf(fmaxf(s_max[0][c], s_max[1][c]), fmaxf(s_max[2][c], s_max[3][c]));
        g_pool[b * 256 + c] = sum * (1.f / 256.f);
        g_pool[b * 256 + cCH + c] = mx;
    }
}

// ---------------- 6) final MLP (block per batch) ----------------
__global__ __launch_bounds__(256) void mlp_kernel(const float* __restrict__ x,
                                                  const float* __restrict__ We1, const float* __restrict__ be1,
                                                  const float* __restrict__ We2, const float* __restrict__ be2,
                                                  const float* __restrict__ We3, const float* __restrict__ be3,
                                                  float* __restrict__ out) {
    __shared__ float s_z[cXD + 256];
    __shared__ float s_h1[256];
    __shared__ float s_h2[32];
    const int b = blockIdx.x, t = threadIdx.x;
    for (int i = t; i < cXD; i += 256) s_z[i] = x[b * cXD + i];
    s_z[cXD + t] = g_pool[b * 256 + t];
    __syncthreads();
    {
        float a0 = 0.f, a1 = 0.f, a2 = 0.f, a3 = 0.f;
#pragma unroll 2
        for (int k = 0; k < cXD + 256; k += 4) {
            a0 += s_z[k + 0] * We1[(k + 0) * 256 + t];
            a1 += s_z[k + 1] * We1[(k + 1) * 256 + t];
            a2 += s_z[k + 2] * We1[(k + 2) * 256 + t];
            a3 += s_z[k + 3] * We1[(k + 3) * 256 + t];
        }
        float v = (a0 + a1) + (a2 + a3) + be1[t];
        s_h1[t] = leaky(v);
    }
    __syncthreads();
    if (t < 32) {
        float c0 = 0.f, c1 = 0.f, c2 = 0.f, c3 = 0.f;
        for (int k = 0; k < 256; k += 4) {
            c0 += s_h1[k + 0] * We2[(k + 0) * 32 + t];
            c1 += s_h1[k + 1] * We2[(k + 1) * 32 + t];
            c2 += s_h1[k + 2] * We2[(k + 2) * 32 + t];
            c3 += s_h1[k + 3] * We2[(k + 3) * 32 + t];
        }
        float u = (c0 + c1) + (c2 + c3) + be2[t];
        s_h2[t] = leaky(u);
    }
    __syncthreads();
    if (t < 32) {
        float p = s_h2[t] * We3[t];
#pragma unroll
        for (int o = 16; o; o >>= 1) p += __shfl_xor_sync(0xffffffffu, p, o);
        if (t == 0) out[b] = p + be3[0];
    }
}

// ---------------- launch ----------------
extern "C" void kernel_launch(void* const* d_in, const int* in_sizes, int n_in,
                              void* d_out, int out_size) {
    const float* x       = (const float*)d_in[0];
    const float* y_atoms = (const float*)d_in[1];
    const int*   y_bonds = (const int*)d_in[2];
    const float* W1 = (const float*)d_in[3];
    const float* b1 = (const float*)d_in[4];
    const float* a1 = (const float*)d_in[5];
    const float* W2 = (const float*)d_in[6];
    const float* b2 = (const float*)d_in[7];
    const float* a2 = (const float*)d_in[8];
    const float* W3 = (const float*)d_in[9];
    const float* b3 = (const float*)d_in[10];
    const float* a3 = (const float*)d_in[11];
    const float* We1 = (const float*)d_in[12];
    const float* be1 = (const float*)d_in[13];
    const float* We2 = (const float*)d_in[14];
    const float* be2 = (const float*)d_in[15];
    const float* We3 = (const float*)d_in[16];
    const float* be3 = (const float*)d_in[17];
    float* out = (float*)d_out;

    cudaFuncSetAttribute((const void*)attn_kernel<true>,
                         cudaFuncAttributeMaxDynamicSharedMemorySize, ATTN_SMEM);
    cudaFuncSetAttribute((const void*)attn_kernel<false>,
                         cudaFuncAttributeMaxDynamicSharedMemorySize, ATTN_SMEM);

    float* atoms_ptr = nullptr;
    cudaGetSymbolAddress((void**)&atoms_ptr, g_atoms);

    const dim3 gemm_grid(10, 128);
    const int attn_grid = cB * N_ITILES;   // 256

    pack_mask_kernel<<<(cB * cN * MASK_WORDS_PER_ROW + 255) / 256, 256>>>(y_bonds);

    // layer 1
    gemm_bias_kernel<cCIN><<<gemm_grid, 256>>>(y_atoms, W1, b1);
    src_dst_kernel<<<cB * cN, 160>>>(a1);
    attn_kernel<true><<<attn_grid, 256, ATTN_SMEM>>>();
    // layer 2
    gemm_bias_kernel<cCH><<<gemm_grid, 256>>>(atoms_ptr, W2, b2);
    src_dst_kernel<<<cB * cN, 160>>>(a2);
    attn_kernel<true><<<attn_grid, 256, ATTN_SMEM>>>();
    // layer 3
    gemm_bias_kernel<cCH><<<gemm_grid, 256>>>(atoms_ptr, W3, b3);
    src_dst_kernel<<<cB * cN, 160>>>(a3);
    attn_kernel<false><<<attn_grid, 256, ATTN_SMEM>>>();

    pool_kernel<<<cB, 512>>>();
    mlp_kernel<<<cB, 256>>>(x, We1, be1, We2, be2, We3, be3, out);
}